// round 7
// baseline (speedup 1.0000x reference)
#include <cuda_runtime.h>
#include <math.h>

// Problem constants
#define BB 4
#define NN 1024
#define CC 128
#define HH 256
#define WW 256
#define MM 1024
#define GRIDC 8

#define TQ 64
#define TMC 64
#define MSPLIT 2
#define COLS_PER_SPLIT (MM / MSPLIT)      // 512
#define CHUNKS (COLS_PER_SPLIT / TMC)     // 8
#define QTILES (NN / TQ)                  // 16
#define HALF_BLOCKS (BB * QTILES * MSPLIT) // 128
#define MAIN_BLOCKS (2 * HALF_BLOCKS)      // 256
#define NTOP (MSPLIT * 8)                  // 16 per row

// k-pair tile layout: [64 kpairs][64 rows] of float2 (no pad; 512B rows)
// aT2: 32KB, gT2: 32KB, wc: 512B  -> ~64.6KB, 2 blocks/SM easily
#define TILE_FLOATS (64 * 64 * 2)
#define SMEM_FLOATS (2 * TILE_FLOATS + 2 * TMC)
#define SMEM_BYTES (SMEM_FLOATS * 4)

#define FMA2(acc, a, b) asm("fma.rn.f32x2 %0, %1, %2, %0;" : "+l"(acc) : "l"(a), "l"(b))
#define UNPACK2(lo, hi, v) asm("mov.b64 {%0, %1}, %2;" : "=f"(lo), "=f"(hi) : "l"(v))

// Scratch (device globals)
__device__ float g_a [BB * NN * CC];
__device__ float g_wa[BB * NN * CC];
__device__ float g_gd[BB * MM * CC];
__device__ float g_fos_top [BB * NN * NTOP];   // dots
__device__ float g_sos_topv[BB * NN * NTOP];   // dots
__device__ int   g_sos_topi[BB * NN * NTOP];
__device__ float g_fos_row[BB * NN];
__device__ float g_vis_row[BB * NN];
__device__ float g_sos_row[BB * NN];

// ---------------------------------------------------------------------------
// Prep kernels (3 launches so main_kernel is launch #4 for ncu)
// ---------------------------------------------------------------------------
__global__ void prep_a_kernel(const float* __restrict__ kp1_desc) {
    int c = threadIdx.x;
    float v = kp1_desc[(size_t)blockIdx.x * CC + c];
    __shared__ float red[4];
    float s = v * v;
    #pragma unroll
    for (int o = 16; o > 0; o >>= 1) s += __shfl_down_sync(0xffffffffu, s, o);
    if ((c & 31) == 0) red[c >> 5] = s;
    __syncthreads();
    float tot = red[0] + red[1] + red[2] + red[3];
    g_a[(size_t)blockIdx.x * CC + c] = v / (sqrtf(tot) + 1e-8f);
}

template<bool GD>
__global__ void prep_bil_kernel(const float* __restrict__ w_kp1,
                                const float* __restrict__ desc2) {
    int idx = blockIdx.x;
    int c = threadIdx.x;
    int b;
    float px, py;
    if (GD) {
        b = idx / MM; int m = idx - b * MM;
        px = ((float)(m & 31) + 0.5f) * (float)GRIDC;
        py = ((float)(m >> 5) + 0.5f) * (float)GRIDC;
    } else {
        b = idx / NN; int n = idx - b * NN;
        px = w_kp1[(size_t)(b * NN + n) * 2 + 0];
        py = w_kp1[(size_t)(b * NN + n) * 2 + 1];
    }
    float x = fminf(fmaxf(px, 0.0f), (float)(WW - 1));
    float y = fminf(fmaxf(py, 0.0f), (float)(HH - 1));
    float x0f = floorf(x), y0f = floorf(y);
    float wx = x - x0f, wy = y - y0f;
    int x0 = (int)x0f, y0 = (int)y0f;
    int x1 = min(x0 + 1, WW - 1), y1 = min(y0 + 1, HH - 1);
    const float* base = desc2 + (size_t)(b * CC + c) * (HH * WW);
    float v00 = base[y0 * WW + x0];
    float v01 = base[y0 * WW + x1];
    float v10 = base[y1 * WW + x0];
    float v11 = base[y1 * WW + x1];
    float v = v00 * (1.0f - wy) * (1.0f - wx) + v01 * (1.0f - wy) * wx
            + v10 * wy * (1.0f - wx)          + v11 * wy * wx;

    __shared__ float red[4];
    float s = v * v;
    #pragma unroll
    for (int o = 16; o > 0; o >>= 1) s += __shfl_down_sync(0xffffffffu, s, o);
    if ((c & 31) == 0) red[c >> 5] = s;
    __syncthreads();
    float tot = red[0] + red[1] + red[2] + red[3];
    float* dst = GD ? g_gd : g_wa;
    dst[(size_t)idx * CC + c] = v / (sqrtf(tot) + 1e-8f);
}

// ---------------------------------------------------------------------------
__device__ __forceinline__ float compute_vis(const float* __restrict__ kp1,
                                             const float* __restrict__ homo,
                                             int b, int n) {
    float kx = kp1[(size_t)(b * NN + n) * 2 + 0];
    float ky = kp1[(size_t)(b * NN + n) * 2 + 1];
    const float* hm = homo + b * 9;
    float den = hm[6] * kx + hm[7] * ky + hm[8] + 1e-8f;
    float wkx = (hm[0] * kx + hm[1] * ky + hm[2]) / den;
    float wky = (hm[3] * kx + hm[4] * ky + hm[5]) / den;
    return (wkx >= 0.0f && wkx <= (float)(WW - 1) &&
            wky >= 0.0f && wky <= (float)(HH - 1)) ? 1.0f : 0.0f;
}

// ---------------------------------------------------------------------------
// Store a float4 (row r, k-quad k4) into k-pair layout [kp][r] float2.
// ---------------------------------------------------------------------------
__device__ __forceinline__ void store_kpair(float* tile, int r, int k4, float4 v) {
    *(float2*)(tile + ((size_t)(2 * k4) * 64 + r) * 2)     = make_float2(v.x, v.y);
    *(float2*)(tile + ((size_t)(2 * k4 + 1) * 64 + r) * 2) = make_float2(v.z, v.w);
}

// ---------------------------------------------------------------------------
// Main kernel. Blocks [0,128): FOS; [128,256): SOS.
// k-pair f32x2 dot loop (no packs), register-transpose selection, occ 2.
// ---------------------------------------------------------------------------
__global__ __launch_bounds__(256, 2) void main_kernel(const float* __restrict__ w_kp1) {
    extern __shared__ float sm[];
    float* aT2 = sm;                     // [64 kp][64 r] float2
    float* gT2 = aT2 + TILE_FLOATS;      // [64 kp][64 c] float2
    float* wc  = gT2 + TILE_FLOATS;      // [64][2]

    int tid = threadIdx.x;
    int lane = tid & 31;
    int warp = tid >> 5;
    int bid = blockIdx.x;
    bool is_sos = bid >= HALF_BLOCKS;
    int lbid = is_sos ? bid - HALF_BLOCKS : bid;
    int ms = lbid & (MSPLIT - 1);
    int qt = (lbid >> 1) & (QTILES - 1);
    int b  = lbid >> 5;
    int n0 = qt * TQ;
    int m_base = ms * COLS_PER_SPLIT;

    const float* qsrc = is_sos ? g_wa : g_a;
    const float* csrc = is_sos ? g_wa : g_gd;
    const int crows = is_sos ? NN : MM;

    // query tile -> k-pair layout
    for (int idx = tid; idx < TQ * 32; idx += 256) {
        int r = idx & 63, k4 = idx >> 6;
        float4 v = *(const float4*)&qsrc[(size_t)(b * NN + n0 + r) * CC + 4 * k4];
        store_kpair(aT2, r, k4, v);
    }

    // selection identity (register transpose target)
    int Rl = lane >> 2;             // row within warp's 8 rows
    int qq = lane & 3;              // col quarter (16 cols)
    int r_d = Rl & 3;
    int s_base = ((Rl >> 2) << 4) + 4 * qq;
    int row_loc = 8 * warp + Rl;
    int n_glob = n0 + row_loc;
    float qx = w_kp1[(size_t)(b * NN + n_glob) * 2 + 0];
    float qy = w_kp1[(size_t)(b * NN + n_glob) * 2 + 1];

    float vals[8];
    int   idxs[8];
    #pragma unroll
    for (int j = 0; j < 8; j++) { vals[j] = -1e30f; idxs[j] = 0; }
    float worst = -1e30f;

    int tx = tid & 15, ty = tid >> 4;

    // prefetch chunk 0 (first half)
    float4 pf[4];
    #pragma unroll
    for (int j = 0; j < 4; j++) {
        int idx = tid + j * 256; int r = idx & 63, k4 = idx >> 6;
        pf[j] = *(const float4*)&csrc[(size_t)(b * crows + m_base + r) * CC + 4 * k4];
    }

    for (int ch = 0; ch < CHUNKS; ch++) {
        int m0 = m_base + ch * TMC;
        __syncthreads();   // B1: gT2/wc free
        #pragma unroll
        for (int j = 0; j < 4; j++) {
            int idx = tid + j * 256; int r = idx & 63, k4 = idx >> 6;
            store_kpair(gT2, r, k4, pf[j]);
        }
        #pragma unroll
        for (int j = 4; j < 8; j++) {
            int idx = tid + j * 256; int r = idx & 63, k4 = idx >> 6;
            float4 v = *(const float4*)&csrc[(size_t)(b * crows + m0 + r) * CC + 4 * k4];
            store_kpair(gT2, r, k4, v);
        }
        if (is_sos && tid < 128) wc[tid] = w_kp1[(size_t)(b * NN + m0) * 2 + tid];
        __syncthreads();   // B2: tile ready

        if (ch + 1 < CHUNKS) {
            #pragma unroll
            for (int j = 0; j < 4; j++) {
                int idx = tid + j * 256; int r = idx & 63, k4 = idx >> 6;
                pf[j] = *(const float4*)&csrc[(size_t)(b * crows + m0 + TMC + r) * CC + 4 * k4];
            }
        }

        // k-pair f32x2 dot: 16 accs, no packs. 4 LDS.128 + 16 FMA2 per kp.
        unsigned long long acc[16];
        #pragma unroll
        for (int j = 0; j < 16; j++) acc[j] = 0ULL;
        const ulonglong2* ap = (const ulonglong2*)(aT2 + 8 * ty);  // rows 4ty..
        const ulonglong2* gp = (const ulonglong2*)(gT2 + 8 * tx);  // cols 4tx..
        #pragma unroll 4
        for (int kp = 0; kp < 64; kp++) {
            ulonglong2 a01 = ap[kp * 32];
            ulonglong2 a23 = ap[kp * 32 + 1];
            ulonglong2 g01 = gp[kp * 32];
            ulonglong2 g23 = gp[kp * 32 + 1];
            FMA2(acc[ 0], a01.x, g01.x); FMA2(acc[ 1], a01.x, g01.y);
            FMA2(acc[ 2], a01.x, g23.x); FMA2(acc[ 3], a01.x, g23.y);
            FMA2(acc[ 4], a01.y, g01.x); FMA2(acc[ 5], a01.y, g01.y);
            FMA2(acc[ 6], a01.y, g23.x); FMA2(acc[ 7], a01.y, g23.y);
            FMA2(acc[ 8], a23.x, g01.x); FMA2(acc[ 9], a23.x, g01.y);
            FMA2(acc[10], a23.x, g23.x); FMA2(acc[11], a23.x, g23.y);
            FMA2(acc[12], a23.y, g01.x); FMA2(acc[13], a23.y, g01.y);
            FMA2(acc[14], a23.y, g23.x); FMA2(acc[15], a23.y, g23.y);
        }

        // horizontal add: dot[r][c] = lo + hi
        float dot[16];
        #pragma unroll
        for (int j = 0; j < 16; j++) {
            float lo, hi; UNPACK2(lo, hi, acc[j]);
            dot[j] = lo + hi;
        }

        // intra-warp transpose: lane -> 1 row x 16 cols
        float my[16];
        #pragma unroll
        for (int r = 0; r < 4; r++) {
            #pragma unroll
            for (int c = 0; c < 4; c++) {
                #pragma unroll
                for (int off = 0; off < 4; off++) {
                    float v = __shfl_sync(0xffffffffu, dot[r * 4 + c], s_base + off);
                    if (r_d == r) my[4 * off + c] = v;
                }
            }
        }

        // mask + insert into per-lane top-8 (dot domain; masked = -1e30)
        #pragma unroll
        for (int i = 0; i < 16; i++) {
            int col = 16 * qq + i;
            int m = m0 + col;
            float cx, cy; bool em = false;
            if (is_sos) {
                cx = wc[2 * col]; cy = wc[2 * col + 1];
                em = (m == n_glob);
            } else {
                cx = (float)((m & 31) * GRIDC + 4);
                cy = (float)((m >> 5) * GRIDC + 4);
            }
            float dx = qx - cx, dy = qy - cy;
            float val = ((dx * dx + dy * dy < 256.0f) || em) ? -1e30f : my[i];
            if (val > worst) {
                bool done = false;
                #pragma unroll
                for (int j = 0; j < 8; j++)
                    if (!done && vals[j] == worst) {
                        vals[j] = val; idxs[j] = m; done = true;
                    }
                worst = vals[0];
                #pragma unroll
                for (int j = 1; j < 8; j++) worst = fminf(worst, vals[j]);
            }
        }
    }

    // endgame: stage 4 lanes x 8 candidates per row into freed gT2
    __syncthreads();
    float* sgv = gT2;                         // [64][32]
    int*   sgi = (int*)(gT2 + 64 * 32);       // [64][32]
    {
        float* pv = sgv + row_loc * 32 + qq * 8;
        int*   pi = sgi + row_loc * 32 + qq * 8;
        #pragma unroll
        for (int j = 0; j < 8; j++) { pv[j] = vals[j]; pi[j] = idxs[j]; }
    }
    __syncthreads();

    if (tid < TQ) {
        float mv[8]; int mi[8];
        #pragma unroll
        for (int j = 0; j < 8; j++) { mv[j] = -1e30f; mi[j] = 0; }
        float w8 = -1e30f;
        const float* pv = sgv + tid * 32;
        const int*   pi = sgi + tid * 32;
        #pragma unroll 4
        for (int i = 0; i < 32; i++) {
            float val = pv[i];
            if (val > w8) {
                int ii = pi[i];
                bool done = false;
                #pragma unroll
                for (int j = 0; j < 8; j++)
                    if (!done && mv[j] == w8) { mv[j] = val; mi[j] = ii; done = true; }
                w8 = mv[0];
                #pragma unroll
                for (int j = 1; j < 8; j++) w8 = fminf(w8, mv[j]);
            }
        }
        size_t base = (size_t)(b * NN + n0 + tid) * NTOP + ms * 8;
        if (is_sos) {
            #pragma unroll
            for (int j = 0; j < 8; j++) {
                g_sos_topv[base + j] = mv[j];
                g_sos_topi[base + j] = mi[j];
            }
        } else {
            #pragma unroll
            for (int j = 0; j < 8; j++) g_fos_top[base + j] = mv[j];
        }
    }
}

// ---------------------------------------------------------------------------
__device__ __forceinline__ void bitonic32(float& v, int& i) {
    unsigned lane = threadIdx.x & 31;
    #pragma unroll
    for (int k = 2; k <= 32; k <<= 1) {
        #pragma unroll
        for (int j = k >> 1; j > 0; j >>= 1) {
            float pv = __shfl_xor_sync(0xffffffffu, v, j);
            int   pi = __shfl_xor_sync(0xffffffffu, i, j);
            bool up = ((lane & k) == 0) || (k == 32);
            bool keepmin = (up == ((lane & j) == 0));
            bool take = keepmin ? (pv < v) : (pv > v);
            if (take) { v = pv; i = pi; }
        }
    }
}

// ---------------------------------------------------------------------------
// Epilogue: warp per row; dot-domain merges (sort -dot asc), pos, vis, d1.
// ---------------------------------------------------------------------------
__global__ __launch_bounds__(256) void epilogue_kernel(const float* __restrict__ kp1,
                                                       const float* __restrict__ homo) {
    int w = threadIdx.x >> 5, lane = threadIdx.x & 31;
    int row = blockIdx.x * 8 + w;
    int b = row >> 10, n = row & 1023;

    float4 av = *(const float4*)&g_a [(size_t)row * CC + 4 * lane];
    float4 wv = *(const float4*)&g_wa[(size_t)row * CC + 4 * lane];
    float d0 = av.x - wv.x, d1 = av.y - wv.y, d2 = av.z - wv.z, d3 = av.w - wv.w;
    float s = d0 * d0 + d1 * d1 + d2 * d2 + d3 * d3;
    #pragma unroll
    for (int o = 16; o > 0; o >>= 1) s += __shfl_xor_sync(0xffffffffu, s, o);
    float pos = sqrtf(s);

    // ---- FOS: 16 partials, pad rest ----
    float fneg = (lane < NTOP) ? -g_fos_top[(size_t)row * NTOP + lane] : 1e30f;
    int   fdmy = 0;
    bitonic32(fneg, fdmy);
    float fdist = (fneg > 1e29f) ? 10.0f
                                 : sqrtf(fmaxf(2.0f + 2.0f * fneg, 0.0f) + 1e-8f);
    float f = (lane < 8) ? fmaxf(pos - fdist + 1.0f, 0.0f) : 0.0f;
    #pragma unroll
    for (int o = 16; o > 0; o >>= 1) f += __shfl_xor_sync(0xffffffffu, f, o);

    // ---- SOS ----
    float sneg = (lane < NTOP) ? -g_sos_topv[(size_t)row * NTOP + lane] : 1e30f;
    int   si   = (lane < NTOP) ?  g_sos_topi[(size_t)row * NTOP + lane] : 0;
    bitonic32(sneg, si);

    int j = lane >> 2, q = lane & 3;
    float d2neg = __shfl_sync(0xffffffffu, sneg, j);
    int   cidx  = __shfl_sync(0xffffffffu, si, j);
    const float4* pa = (const float4*)(g_a + (size_t)row * CC);
    const float4* pb = (const float4*)(g_a + (size_t)(b * NN + cidx) * CC);
    float dp = 0.0f;
    #pragma unroll
    for (int kk = 0; kk < 8; kk++) {
        float4 x = pa[q * 8 + kk], y = pb[q * 8 + kk];
        dp += x.x * y.x + x.y * y.y + x.z * y.z + x.w * y.w;
    }
    dp += __shfl_xor_sync(0xffffffffu, dp, 1);
    dp += __shfl_xor_sync(0xffffffffu, dp, 2);
    float d1v = sqrtf(fmaxf(2.0f - 2.0f * dp, 0.0f) + 1e-8f);
    float d2v = sqrtf(fmaxf(2.0f + 2.0f * d2neg, 0.0f) + 1e-8f);
    float t = (d2neg < 1e29f) ? (d1v - d2v) : 0.0f;
    float t2 = (q == 0) ? t * t : 0.0f;
    #pragma unroll
    for (int o = 16; o > 0; o >>= 1) t2 += __shfl_xor_sync(0xffffffffu, t2, o);

    if (lane == 0) {
        float vis = compute_vis(kp1, homo, b, n);
        g_fos_row[row] = f * vis;
        g_vis_row[row] = vis;
        g_sos_row[row] = sqrtf(t2 + 1e-8f) * vis;
    }
}

// ---------------------------------------------------------------------------
__global__ void finalize_kernel(float* __restrict__ out) {
    __shared__ float sf[1024], sv[1024], ss[1024];
    int t = threadIdx.x;
    float f = 0.0f, v = 0.0f, s = 0.0f;
    #pragma unroll
    for (int i = 0; i < 4; i++) {
        f += g_fos_row[t + 1024 * i];
        v += g_vis_row[t + 1024 * i];
        s += g_sos_row[t + 1024 * i];
    }
    sf[t] = f; sv[t] = v; ss[t] = s;
    __syncthreads();
    for (int o = 512; o > 0; o >>= 1) {
        if (t < o) {
            sf[t] += sf[t + o];
            sv[t] += sv[t + o];
            ss[t] += ss[t + o];
        }
        __syncthreads();
    }
    if (t == 0) {
        float cnt = fmaxf(sv[0], 1.0f);
        out[0] = sf[0] / (cnt * 8.0f) + ss[0] / cnt;
    }
}

// ---------------------------------------------------------------------------
extern "C" void kernel_launch(void* const* d_in, const int* in_sizes, int n_in,
                              void* d_out, int out_size) {
    const float* kp1      = (const float*)d_in[0];
    const float* w_kp1    = (const float*)d_in[1];
    const float* kp1_desc = (const float*)d_in[2];
    const float* desc2    = (const float*)d_in[3];
    const float* homo12   = (const float*)d_in[4];
    (void)in_sizes; (void)n_in; (void)out_size;

    cudaFuncSetAttribute(main_kernel,
                         cudaFuncAttributeMaxDynamicSharedMemorySize, SMEM_BYTES);

    prep_a_kernel<<<BB * NN, CC>>>(kp1_desc);
    prep_bil_kernel<false><<<BB * NN, CC>>>(w_kp1, desc2);
    prep_bil_kernel<true ><<<BB * MM, CC>>>(w_kp1, desc2);
    main_kernel<<<MAIN_BLOCKS, 256, SMEM_BYTES>>>(w_kp1);
    epilogue_kernel<<<BB * NN / 8, 256>>>(kp1, homo12);
    finalize_kernel<<<1, 1024>>>((float*)d_out);
}

// round 8
// speedup vs baseline: 1.0015x; 1.0015x over previous
#include <cuda_runtime.h>
#include <math.h>

// Problem constants
#define BB 4
#define NN 1024
#define CC 128
#define HH 256
#define WW 256
#define MM 1024
#define GRIDC 8

#define TQ 64
#define TMC 64
#define MSPLIT 2
#define COLS_PER_SPLIT (MM / MSPLIT)      // 512
#define CHUNKS (COLS_PER_SPLIT / TMC)     // 8
#define QTILES (NN / TQ)                  // 16
#define HALF_BLOCKS (BB * QTILES * MSPLIT) // 128
#define MAIN_BLOCKS (2 * HALF_BLOCKS)      // 256
#define NTOP (MSPLIT * 8)                  // 16 per row

// k-pair tile layout: [64 kpairs][64 slots] float2, row = 128 floats (512B)
#define TILE_FLOATS (64 * 64 * 2)
#define SMEM_FLOATS (2 * TILE_FLOATS + 2 * TMC)
#define SMEM_BYTES (SMEM_FLOATS * 4)

#define FMA2(acc, a, b) asm("fma.rn.f32x2 %0, %1, %2, %0;" : "+l"(acc) : "l"(a), "l"(b))
#define UNPACK2(lo, hi, v) asm("mov.b64 {%0, %1}, %2;" : "=f"(lo), "=f"(hi) : "l"(v))

// Scratch (device globals)
__device__ float g_a [BB * NN * CC];
__device__ float g_wa[BB * NN * CC];
__device__ float g_gd[BB * MM * CC];
__device__ float g_fos_top [BB * NN * NTOP];   // dots
__device__ float g_sos_topv[BB * NN * NTOP];   // dots
__device__ int   g_sos_topi[BB * NN * NTOP];
__device__ float g_fos_row[BB * NN];
__device__ float g_vis_row[BB * NN];
__device__ float g_sos_row[BB * NN];

// ---------------------------------------------------------------------------
// Prep kernels (3 launches so main_kernel is launch #4 for ncu)
// ---------------------------------------------------------------------------
__global__ void prep_a_kernel(const float* __restrict__ kp1_desc) {
    int c = threadIdx.x;
    float v = kp1_desc[(size_t)blockIdx.x * CC + c];
    __shared__ float red[4];
    float s = v * v;
    #pragma unroll
    for (int o = 16; o > 0; o >>= 1) s += __shfl_down_sync(0xffffffffu, s, o);
    if ((c & 31) == 0) red[c >> 5] = s;
    __syncthreads();
    float tot = red[0] + red[1] + red[2] + red[3];
    g_a[(size_t)blockIdx.x * CC + c] = v / (sqrtf(tot) + 1e-8f);
}

template<bool GD>
__global__ void prep_bil_kernel(const float* __restrict__ w_kp1,
                                const float* __restrict__ desc2) {
    int idx = blockIdx.x;
    int c = threadIdx.x;
    int b;
    float px, py;
    if (GD) {
        b = idx / MM; int m = idx - b * MM;
        px = ((float)(m & 31) + 0.5f) * (float)GRIDC;
        py = ((float)(m >> 5) + 0.5f) * (float)GRIDC;
    } else {
        b = idx / NN; int n = idx - b * NN;
        px = w_kp1[(size_t)(b * NN + n) * 2 + 0];
        py = w_kp1[(size_t)(b * NN + n) * 2 + 1];
    }
    float x = fminf(fmaxf(px, 0.0f), (float)(WW - 1));
    float y = fminf(fmaxf(py, 0.0f), (float)(HH - 1));
    float x0f = floorf(x), y0f = floorf(y);
    float wx = x - x0f, wy = y - y0f;
    int x0 = (int)x0f, y0 = (int)y0f;
    int x1 = min(x0 + 1, WW - 1), y1 = min(y0 + 1, HH - 1);
    const float* base = desc2 + (size_t)(b * CC + c) * (HH * WW);
    float v00 = base[y0 * WW + x0];
    float v01 = base[y0 * WW + x1];
    float v10 = base[y1 * WW + x0];
    float v11 = base[y1 * WW + x1];
    float v = v00 * (1.0f - wy) * (1.0f - wx) + v01 * (1.0f - wy) * wx
            + v10 * wy * (1.0f - wx)          + v11 * wy * wx;

    __shared__ float red[4];
    float s = v * v;
    #pragma unroll
    for (int o = 16; o > 0; o >>= 1) s += __shfl_down_sync(0xffffffffu, s, o);
    if ((c & 31) == 0) red[c >> 5] = s;
    __syncthreads();
    float tot = red[0] + red[1] + red[2] + red[3];
    float* dst = GD ? g_gd : g_wa;
    dst[(size_t)idx * CC + c] = v / (sqrtf(tot) + 1e-8f);
}

// ---------------------------------------------------------------------------
__device__ __forceinline__ float compute_vis(const float* __restrict__ kp1,
                                             const float* __restrict__ homo,
                                             int b, int n) {
    float kx = kp1[(size_t)(b * NN + n) * 2 + 0];
    float ky = kp1[(size_t)(b * NN + n) * 2 + 1];
    const float* hm = homo + b * 9;
    float den = hm[6] * kx + hm[7] * ky + hm[8] + 1e-8f;
    float wkx = (hm[0] * kx + hm[1] * ky + hm[2]) / den;
    float wky = (hm[3] * kx + hm[4] * ky + hm[5]) / den;
    return (wkx >= 0.0f && wkx <= (float)(WW - 1) &&
            wky >= 0.0f && wky <= (float)(HH - 1)) ? 1.0f : 0.0f;
}

// ---------------------------------------------------------------------------
// Store a float4 (slot r, k-quad k4) into k-pair layout [kp][slot] float2.
// ---------------------------------------------------------------------------
__device__ __forceinline__ void store_kpair(float* tile, int r, int k4, float4 v) {
    *(float2*)(tile + ((size_t)(2 * k4) * 64 + r) * 2)     = make_float2(v.x, v.y);
    *(float2*)(tile + ((size_t)(2 * k4 + 1) * 64 + r) * 2) = make_float2(v.z, v.w);
}

// ---------------------------------------------------------------------------
// Main kernel. Blocks [0,128): FOS; [128,256): SOS.
// Thread (rp=tid>>3, u=tid&7): rows {2rp,2rp+1}, cols {2u+16m, 2u+1+16m}.
// Conflict-free LDS; per-thread row-local top-8 (no transpose, no staging).
// ---------------------------------------------------------------------------
__global__ __launch_bounds__(256, 2) void main_kernel(const float* __restrict__ w_kp1) {
    extern __shared__ float sm[];
    float* aT2 = sm;                     // [64 kp][64 rows] float2
    float* gT2 = aT2 + TILE_FLOATS;      // [64 kp][64 cols] float2
    float* wc  = gT2 + TILE_FLOATS;      // [64][2]

    int tid = threadIdx.x;
    int bid = blockIdx.x;
    bool is_sos = bid >= HALF_BLOCKS;
    int lbid = is_sos ? bid - HALF_BLOCKS : bid;
    int ms = lbid & (MSPLIT - 1);
    int qt = (lbid >> 1) & (QTILES - 1);
    int b  = lbid >> 5;
    int n0 = qt * TQ;
    int m_base = ms * COLS_PER_SPLIT;

    const float* qsrc = is_sos ? g_wa : g_a;
    const float* csrc = is_sos ? g_wa : g_gd;
    const int crows = is_sos ? NN : MM;

    // query tile -> k-pair layout
    for (int idx = tid; idx < TQ * 32; idx += 256) {
        int r = idx & 63, k4 = idx >> 6;
        float4 v = *(const float4*)&qsrc[(size_t)(b * NN + n0 + r) * CC + 4 * k4];
        store_kpair(aT2, r, k4, v);
    }

    // ownership
    int u  = tid & 7;          // col group
    int rp = tid >> 3;         // row pair 0..31
    int row0 = 2 * rp, row1 = 2 * rp + 1;
    int ng0 = n0 + row0, ng1 = n0 + row1;
    float qx0 = w_kp1[(size_t)(b * NN + ng0) * 2 + 0];
    float qy0 = w_kp1[(size_t)(b * NN + ng0) * 2 + 1];
    float qx1 = w_kp1[(size_t)(b * NN + ng1) * 2 + 0];
    float qy1 = w_kp1[(size_t)(b * NN + ng1) * 2 + 1];

    float vals[2][8];
    int   idxs[2][8];
    float worst[2];
    #pragma unroll
    for (int r = 0; r < 2; r++) {
        #pragma unroll
        for (int j = 0; j < 8; j++) { vals[r][j] = -1e30f; idxs[r][j] = 0; }
        worst[r] = -1e30f;
    }

    // prefetch chunk 0 (first half)
    float4 pf[4];
    #pragma unroll
    for (int j = 0; j < 4; j++) {
        int idx = tid + j * 256; int r = idx & 63, k4 = idx >> 6;
        pf[j] = *(const float4*)&csrc[(size_t)(b * crows + m_base + r) * CC + 4 * k4];
    }

    for (int ch = 0; ch < CHUNKS; ch++) {
        int m0 = m_base + ch * TMC;
        __syncthreads();   // B1: gT2/wc free
        #pragma unroll
        for (int j = 0; j < 4; j++) {
            int idx = tid + j * 256; int r = idx & 63, k4 = idx >> 6;
            store_kpair(gT2, r, k4, pf[j]);
        }
        #pragma unroll
        for (int j = 4; j < 8; j++) {
            int idx = tid + j * 256; int r = idx & 63, k4 = idx >> 6;
            float4 v = *(const float4*)&csrc[(size_t)(b * crows + m0 + r) * CC + 4 * k4];
            store_kpair(gT2, r, k4, v);
        }
        if (is_sos && tid < 128) wc[tid] = w_kp1[(size_t)(b * NN + m0) * 2 + tid];
        __syncthreads();   // B2: tile ready

        if (ch + 1 < CHUNKS) {
            #pragma unroll
            for (int j = 0; j < 4; j++) {
                int idx = tid + j * 256; int r = idx & 63, k4 = idx >> 6;
                pf[j] = *(const float4*)&csrc[(size_t)(b * crows + m0 + TMC + r) * CC + 4 * k4];
            }
        }

        // dot loop: 2 rows x 8 cols, f32x2 over k-pairs.
        // a: 1 LDS.128 (rows 2rp,2rp+1); g: 4 LDS.128 (cols 2u+16m, 2u+1+16m)
        unsigned long long acc[2][8];
        #pragma unroll
        for (int r = 0; r < 2; r++)
            #pragma unroll
            for (int j = 0; j < 8; j++) acc[r][j] = 0ULL;

        const float* ap = aT2 + 4 * rp;
        const float* gp = gT2 + 4 * u;
        #pragma unroll 4
        for (int kp = 0; kp < 64; kp++) {
            ulonglong2 av = *(const ulonglong2*)(ap + (size_t)kp * 128);
            unsigned long long a0 = av.x, a1 = av.y;
            #pragma unroll
            for (int m = 0; m < 4; m++) {
                ulonglong2 gv = *(const ulonglong2*)(gp + (size_t)kp * 128 + 32 * m);
                FMA2(acc[0][2 * m + 0], a0, gv.x);
                FMA2(acc[0][2 * m + 1], a0, gv.y);
                FMA2(acc[1][2 * m + 0], a1, gv.x);
                FMA2(acc[1][2 * m + 1], a1, gv.y);
            }
        }

        // horizontal add + mask + insert
        #pragma unroll
        for (int r = 0; r < 2; r++) {
            float qx = r ? qx1 : qx0;
            float qy = r ? qy1 : qy0;
            int ng = r ? ng1 : ng0;
            #pragma unroll
            for (int j = 0; j < 8; j++) {
                float lo, hi; UNPACK2(lo, hi, acc[r][j]);
                float d = lo + hi;
                int col = 2 * u + (j & 1) + 16 * (j >> 1);
                int m = m0 + col;
                float cx, cy; bool em = false;
                if (is_sos) {
                    cx = wc[2 * col]; cy = wc[2 * col + 1];
                    em = (m == ng);
                } else {
                    cx = (float)((m & 31) * GRIDC + 4);
                    cy = (float)((m >> 5) * GRIDC + 4);
                }
                float dx = qx - cx, dy = qy - cy;
                float val = ((dx * dx + dy * dy < 256.0f) || em) ? -1e30f : d;
                if (val > worst[r]) {
                    bool done = false;
                    #pragma unroll
                    for (int jj = 0; jj < 8; jj++)
                        if (!done && vals[r][jj] == worst[r]) {
                            vals[r][jj] = val; idxs[r][jj] = m; done = true;
                        }
                    worst[r] = vals[r][0];
                    #pragma unroll
                    for (int jj = 1; jj < 8; jj++) worst[r] = fminf(worst[r], vals[r][jj]);
                }
            }
        }
    }

    // endgame: stage 8 threads x 8 candidates per row into freed gT2
    __syncthreads();
    float* sgv = gT2;                          // [64][64]
    int*   sgi = (int*)(gT2 + 64 * 64);        // [64][64]
    #pragma unroll
    for (int r = 0; r < 2; r++) {
        float* pv = sgv + (2 * rp + r) * 64 + u * 8;
        int*   pi = sgi + (2 * rp + r) * 64 + u * 8;
        #pragma unroll
        for (int j = 0; j < 8; j++) { pv[j] = vals[r][j]; pi[j] = idxs[r][j]; }
    }
    __syncthreads();

    if (tid < TQ) {
        float mv[8]; int mi[8];
        #pragma unroll
        for (int j = 0; j < 8; j++) { mv[j] = -1e30f; mi[j] = 0; }
        float w8 = -1e30f;
        const float* pv = sgv + tid * 64;
        const int*   pi = sgi + tid * 64;
        #pragma unroll 4
        for (int i = 0; i < 64; i++) {
            float val = pv[i];
            if (val > w8) {
                int ii = pi[i];
                bool done = false;
                #pragma unroll
                for (int j = 0; j < 8; j++)
                    if (!done && mv[j] == w8) { mv[j] = val; mi[j] = ii; done = true; }
                w8 = mv[0];
                #pragma unroll
                for (int j = 1; j < 8; j++) w8 = fminf(w8, mv[j]);
            }
        }
        size_t base = (size_t)(b * NN + n0 + tid) * NTOP + ms * 8;
        if (is_sos) {
            #pragma unroll
            for (int j = 0; j < 8; j++) {
                g_sos_topv[base + j] = mv[j];
                g_sos_topi[base + j] = mi[j];
            }
        } else {
            #pragma unroll
            for (int j = 0; j < 8; j++) g_fos_top[base + j] = mv[j];
        }
    }
}

// ---------------------------------------------------------------------------
__device__ __forceinline__ void bitonic32(float& v, int& i) {
    unsigned lane = threadIdx.x & 31;
    #pragma unroll
    for (int k = 2; k <= 32; k <<= 1) {
        #pragma unroll
        for (int j = k >> 1; j > 0; j >>= 1) {
            float pv = __shfl_xor_sync(0xffffffffu, v, j);
            int   pi = __shfl_xor_sync(0xffffffffu, i, j);
            bool up = ((lane & k) == 0) || (k == 32);
            bool keepmin = (up == ((lane & j) == 0));
            bool take = keepmin ? (pv < v) : (pv > v);
            if (take) { v = pv; i = pi; }
        }
    }
}

// ---------------------------------------------------------------------------
// Epilogue: warp per row; dot-domain merges (sort -dot asc), pos, vis, d1.
// ---------------------------------------------------------------------------
__global__ __launch_bounds__(256) void epilogue_kernel(const float* __restrict__ kp1,
                                                       const float* __restrict__ homo) {
    int w = threadIdx.x >> 5, lane = threadIdx.x & 31;
    int row = blockIdx.x * 8 + w;
    int b = row >> 10, n = row & 1023;

    float4 av = *(const float4*)&g_a [(size_t)row * CC + 4 * lane];
    float4 wv = *(const float4*)&g_wa[(size_t)row * CC + 4 * lane];
    float d0 = av.x - wv.x, d1 = av.y - wv.y, d2 = av.z - wv.z, d3 = av.w - wv.w;
    float s = d0 * d0 + d1 * d1 + d2 * d2 + d3 * d3;
    #pragma unroll
    for (int o = 16; o > 0; o >>= 1) s += __shfl_xor_sync(0xffffffffu, s, o);
    float pos = sqrtf(s);

    // ---- FOS: 16 partials, pad rest ----
    float fneg = (lane < NTOP) ? -g_fos_top[(size_t)row * NTOP + lane] : 1e30f;
    int   fdmy = 0;
    bitonic32(fneg, fdmy);
    float fdist = (fneg > 1e29f) ? 10.0f
                                 : sqrtf(fmaxf(2.0f + 2.0f * fneg, 0.0f) + 1e-8f);
    float f = (lane < 8) ? fmaxf(pos - fdist + 1.0f, 0.0f) : 0.0f;
    #pragma unroll
    for (int o = 16; o > 0; o >>= 1) f += __shfl_xor_sync(0xffffffffu, f, o);

    // ---- SOS ----
    float sneg = (lane < NTOP) ? -g_sos_topv[(size_t)row * NTOP + lane] : 1e30f;
    int   si   = (lane < NTOP) ?  g_sos_topi[(size_t)row * NTOP + lane] : 0;
    bitonic32(sneg, si);

    int j = lane >> 2, q = lane & 3;
    float d2neg = __shfl_sync(0xffffffffu, sneg, j);
    int   cidx  = __shfl_sync(0xffffffffu, si, j);
    const float4* pa = (const float4*)(g_a + (size_t)row * CC);
    const float4* pb = (const float4*)(g_a + (size_t)(b * NN + cidx) * CC);
    float dp = 0.0f;
    #pragma unroll
    for (int kk = 0; kk < 8; kk++) {
        float4 x = pa[q * 8 + kk], y = pb[q * 8 + kk];
        dp += x.x * y.x + x.y * y.y + x.z * y.z + x.w * y.w;
    }
    dp += __shfl_xor_sync(0xffffffffu, dp, 1);
    dp += __shfl_xor_sync(0xffffffffu, dp, 2);
    float d1v = sqrtf(fmaxf(2.0f - 2.0f * dp, 0.0f) + 1e-8f);
    float d2v = sqrtf(fmaxf(2.0f + 2.0f * d2neg, 0.0f) + 1e-8f);
    float t = (d2neg < 1e29f) ? (d1v - d2v) : 0.0f;
    float t2 = (q == 0) ? t * t : 0.0f;
    #pragma unroll
    for (int o = 16; o > 0; o >>= 1) t2 += __shfl_xor_sync(0xffffffffu, t2, o);

    if (lane == 0) {
        float vis = compute_vis(kp1, homo, b, n);
        g_fos_row[row] = f * vis;
        g_vis_row[row] = vis;
        g_sos_row[row] = sqrtf(t2 + 1e-8f) * vis;
    }
}

// ---------------------------------------------------------------------------
__global__ void finalize_kernel(float* __restrict__ out) {
    __shared__ float sf[1024], sv[1024], ss[1024];
    int t = threadIdx.x;
    float f = 0.0f, v = 0.0f, s = 0.0f;
    #pragma unroll
    for (int i = 0; i < 4; i++) {
        f += g_fos_row[t + 1024 * i];
        v += g_vis_row[t + 1024 * i];
        s += g_sos_row[t + 1024 * i];
    }
    sf[t] = f; sv[t] = v; ss[t] = s;
    __syncthreads();
    for (int o = 512; o > 0; o >>= 1) {
        if (t < o) {
            sf[t] += sf[t + o];
            sv[t] += sv[t + o];
            ss[t] += ss[t + o];
        }
        __syncthreads();
    }
    if (t == 0) {
        float cnt = fmaxf(sv[0], 1.0f);
        out[0] = sf[0] / (cnt * 8.0f) + ss[0] / cnt;
    }
}

// ---------------------------------------------------------------------------
extern "C" void kernel_launch(void* const* d_in, const int* in_sizes, int n_in,
                              void* d_out, int out_size) {
    const float* kp1      = (const float*)d_in[0];
    const float* w_kp1    = (const float*)d_in[1];
    const float* kp1_desc = (const float*)d_in[2];
    const float* desc2    = (const float*)d_in[3];
    const float* homo12   = (const float*)d_in[4];
    (void)in_sizes; (void)n_in; (void)out_size;

    cudaFuncSetAttribute(main_kernel,
                         cudaFuncAttributeMaxDynamicSharedMemorySize, SMEM_BYTES);

    prep_a_kernel<<<BB * NN, CC>>>(kp1_desc);
    prep_bil_kernel<false><<<BB * NN, CC>>>(w_kp1, desc2);
    prep_bil_kernel<true ><<<BB * MM, CC>>>(w_kp1, desc2);
    main_kernel<<<MAIN_BLOCKS, 256, SMEM_BYTES>>>(w_kp1);
    epilogue_kernel<<<BB * NN / 8, 256>>>(kp1, homo12);
    finalize_kernel<<<1, 1024>>>((float*)d_out);
}